// round 5
// baseline (speedup 1.0000x reference)
#include <cuda_runtime.h>
#include <cuda_bf16.h>
#include <math.h>
#include <stdint.h>

#define Bn 16384
#define En 256
#define Vn 128
#define Tn 16
#define G3 768

#define OUT_UTT  ((size_t)Bn * Tn * Vn)
#define OUT_NOFF (OUT_UTT)
#define OUT_ROFF (OUT_UTT + Bn)

typedef unsigned long long ull;

// ---------------- packed f32x2 helpers (decoder SIMT path) ----------------
__device__ __forceinline__ ull pack2(float x, float y) {
    ull r; asm("mov.b64 %0, {%1, %2};" : "=l"(r) : "f"(x), "f"(y)); return r;
}
__device__ __forceinline__ void unpack2(ull v, float& x, float& y) {
    asm("mov.b64 {%0, %1}, %2;" : "=f"(x), "=f"(y) : "l"(v));
}
__device__ __forceinline__ void fma2(ull& c, ull a, ull b) {
    asm("fma.rn.f32x2 %0, %1, %2, %3;" : "=l"(c) : "l"(a), "l"(b), "l"(c));
}

// ---------------- mma.sync bf16 helper ----------------
__device__ __forceinline__ void mma_bf16(float* c, const uint32_t* a, uint32_t b0, uint32_t b1) {
    asm volatile("mma.sync.aligned.m16n8k16.row.col.f32.bf16.bf16.f32 "
                 "{%0,%1,%2,%3}, {%4,%5,%6,%7}, {%8,%9}, {%0,%1,%2,%3};"
                 : "+f"(c[0]), "+f"(c[1]), "+f"(c[2]), "+f"(c[3])
                 : "r"(a[0]), "r"(a[1]), "r"(a[2]), "r"(a[3]), "r"(b0), "r"(b1));
}
__device__ __forceinline__ uint32_t bfpack(float x, float y) {
    unsigned short lo = __bfloat16_as_ushort(__float2bfloat16_rn(x));
    unsigned short hi = __bfloat16_as_ushort(__float2bfloat16_rn(y));
    return ((uint32_t)hi << 16) | (uint32_t)lo;
}

// ---------------- device scratch ----------------
__device__ float g_h [2][Bn * En];
__device__ float g_he[2][Bn * En];
__device__ float g_Mdec[Vn * G3];
__device__ float g_cdec[G3];
__device__ float g_Menc[Vn * G3];
__device__ float g_cenc[G3];
__device__ __nv_bfloat16 g_eBhi[4 * 192 * En];   // permuted encoder Whh, bf16 hi
__device__ __nv_bfloat16 g_eBlo[4 * 192 * En];   // bf16 lo residual
__device__ int   g_tok [Bn];
__device__ int   g_toks[Tn * Bn];
__device__ int   g_N   [Bn];
__device__ unsigned char g_alive[Bn];

// ---------------- init ----------------
__global__ void k_init(const float* __restrict__ x) {
    int i = blockIdx.x * blockDim.x + threadIdx.x;
    if (i < Bn * En) { g_h[0][i] = x[i]; g_he[0][i] = 0.f; }
    if (i < Bn)      { g_tok[i] = -1; g_alive[i] = 1; g_N[i] = Tn; }
}

__global__ void k_zero_out(float* __restrict__ out) {
    size_t i = (size_t)blockIdx.x * blockDim.x + threadIdx.x;
    if (i < OUT_UTT / 4) reinterpret_cast<float4*>(out)[i] = make_float4(0.f, 0.f, 0.f, 0.f);
}

// ---------------- k_prep: M = (Wih @ Wd2e)^T, cvec = Wih@bd2e + bih ----------------
__global__ void k_prep(const float* __restrict__ Wih, const float* __restrict__ Wd2e,
                       const float* __restrict__ bd2e, const float* __restrict__ bih,
                       float* __restrict__ M, float* __restrict__ cvec) {
    __shared__ float sw[En];
    __shared__ float sb[En];
    const int v  = blockIdx.x;
    const int j0 = blockIdx.y * 64;
    for (int e = threadIdx.x; e < En; e += 256) {
        sw[e] = Wd2e[e * Vn + v];
        if (v == 0) sb[e] = bd2e[e];
    }
    __syncthreads();
    const int warp = threadIdx.x >> 5, lane = threadIdx.x & 31;
#pragma unroll
    for (int jj = 0; jj < 8; jj++) {
        const int j = j0 + warp * 8 + jj;
        const float* wr = Wih + (size_t)j * En;
        float s = 0.f, c = 0.f;
#pragma unroll
        for (int e = lane; e < En; e += 32) {
            float w = wr[e];
            s += w * sw[e];
            if (v == 0) c += w * sb[e];
        }
#pragma unroll
        for (int o = 16; o; o >>= 1) {
            s += __shfl_xor_sync(0xffffffffu, s, o);
            if (v == 0) c += __shfl_xor_sync(0xffffffffu, c, o);
        }
        if (lane == 0) {
            M[v * G3 + j] = s;
            if (v == 0) cvec[j] = bih[j] + c;
        }
    }
}

// ---------------- k_prepB: split+permute encoder Whh into bf16 hi/lo ----------------
// out[w][n][k], n = g*64 + cc  <->  src row g*256 + w*64 + cc
__global__ void k_prepB(const float* __restrict__ Whh,
                        __nv_bfloat16* __restrict__ Bhi, __nv_bfloat16* __restrict__ Blo) {
    int i = blockIdx.x * 256 + threadIdx.x;
    if (i >= 4 * 192 * En) return;
    int w = i / (192 * En);
    int rem = i % (192 * En);
    int n = rem / En;
    int k = rem % En;
    int g = n >> 6, cc = n & 63;
    float x = Whh[(size_t)(g * 256 + w * 64 + cc) * En + k];
    __nv_bfloat16 hi = __float2bfloat16_rn(x);
    Bhi[i] = hi;
    Blo[i] = __float2bfloat16_rn(x - __bfloat162float(hi));
}

__device__ __forceinline__ float sigm(float x) { return 1.f / (1.f + expf(-x)); }

// ================= DECODER (unchanged SIMT fp32 path) =================
__global__ __launch_bounds__(256, 2) void k_gates(
    const float* __restrict__ hin, float* __restrict__ hout,
    const float* __restrict__ Whh, const float* __restrict__ bhh,
    const float* __restrict__ M, const float* __restrict__ cvec,
    const int* __restrict__ tok)
{
    __shared__ float As[2][16][68];
    __shared__ float Ws[2][16][196];
    const int t  = threadIdx.x;
    const int r0 = blockIdx.x * 64;
    const int j0 = blockIdx.y * 64;
    const int ty = t >> 4, tx = t & 15;

    const int lr  = t >> 2;
    const int lkq = (t & 3) * 4;
    const float* Ag  = hin + (size_t)(r0 + lr) * En + lkq;
    const float* Wg0 = Whh + (size_t)(0 * En + j0 + lr) * En + lkq;
    const float* Wg1 = Whh + (size_t)(1 * En + j0 + lr) * En + lkq;
    const float* Wg2 = Whh + (size_t)(2 * En + j0 + lr) * En + lkq;

    float4 av = *(const float4*)Ag;
    float4 w0 = *(const float4*)Wg0;
    float4 w1 = *(const float4*)Wg1;
    float4 w2 = *(const float4*)Wg2;

    ull acc2[3][4][2];
#pragma unroll
    for (int g = 0; g < 3; g++)
#pragma unroll
        for (int i = 0; i < 4; i++) { acc2[g][i][0] = 0ull; acc2[g][i][1] = 0ull; }

    As[0][lkq+0][lr] = av.x; As[0][lkq+1][lr] = av.y; As[0][lkq+2][lr] = av.z; As[0][lkq+3][lr] = av.w;
    Ws[0][lkq+0][lr      ] = w0.x; Ws[0][lkq+1][lr      ] = w0.y; Ws[0][lkq+2][lr      ] = w0.z; Ws[0][lkq+3][lr      ] = w0.w;
    Ws[0][lkq+0][64  + lr] = w1.x; Ws[0][lkq+1][64  + lr] = w1.y; Ws[0][lkq+2][64  + lr] = w1.z; Ws[0][lkq+3][64  + lr] = w1.w;
    Ws[0][lkq+0][128 + lr] = w2.x; Ws[0][lkq+1][128 + lr] = w2.y; Ws[0][lkq+2][128 + lr] = w2.z; Ws[0][lkq+3][128 + lr] = w2.w;
    __syncthreads();

    for (int kt = 0; kt < 16; kt++) {
        const int buf = kt & 1;
        if (kt < 15) {
            av = *(const float4*)(Ag  + (kt + 1) * 16);
            w0 = *(const float4*)(Wg0 + (kt + 1) * 16);
            w1 = *(const float4*)(Wg1 + (kt + 1) * 16);
            w2 = *(const float4*)(Wg2 + (kt + 1) * 16);
        }
#pragma unroll
        for (int k = 0; k < 16; k++) {
            float4 af = *(const float4*)&As[buf][k][ty * 4];
            ull ap[4];
            ap[0] = pack2(af.x, af.x); ap[1] = pack2(af.y, af.y);
            ap[2] = pack2(af.z, af.z); ap[3] = pack2(af.w, af.w);
            ull bp[3][2];
#pragma unroll
            for (int g = 0; g < 3; g++) {
                bp[g][0] = *(const ull*)&Ws[buf][k][g * 64 + tx * 4];
                bp[g][1] = *(const ull*)&Ws[buf][k][g * 64 + tx * 4 + 2];
            }
#pragma unroll
            for (int i = 0; i < 4; i++)
#pragma unroll
                for (int g = 0; g < 3; g++) {
                    fma2(acc2[g][i][0], ap[i], bp[g][0]);
                    fma2(acc2[g][i][1], ap[i], bp[g][1]);
                }
        }
        if (kt < 15) {
            const int nb = buf ^ 1;
            As[nb][lkq+0][lr] = av.x; As[nb][lkq+1][lr] = av.y; As[nb][lkq+2][lr] = av.z; As[nb][lkq+3][lr] = av.w;
            Ws[nb][lkq+0][lr      ] = w0.x; Ws[nb][lkq+1][lr      ] = w0.y; Ws[nb][lkq+2][lr      ] = w0.z; Ws[nb][lkq+3][lr      ] = w0.w;
            Ws[nb][lkq+0][64  + lr] = w1.x; Ws[nb][lkq+1][64  + lr] = w1.y; Ws[nb][lkq+2][64  + lr] = w1.z; Ws[nb][lkq+3][64  + lr] = w1.w;
            Ws[nb][lkq+0][128 + lr] = w2.x; Ws[nb][lkq+1][128 + lr] = w2.y; Ws[nb][lkq+2][128 + lr] = w2.z; Ws[nb][lkq+3][128 + lr] = w2.w;
            __syncthreads();
        }
    }

    float cv[3][4], bh[3][4];
#pragma unroll
    for (int g = 0; g < 3; g++) {
        float4 cf = *(const float4*)(cvec + g * En + j0 + tx * 4);
        cv[g][0]=cf.x; cv[g][1]=cf.y; cv[g][2]=cf.z; cv[g][3]=cf.w;
        float4 bf = *(const float4*)(bhh + g * En + j0 + tx * 4);
        bh[g][0]=bf.x; bh[g][1]=bf.y; bh[g][2]=bf.z; bh[g][3]=bf.w;
    }
#pragma unroll
    for (int i = 0; i < 4; i++) {
        const int rr = r0 + ty * 4 + i;
        const int tk = tok[rr];
        float m[3][4];
        if (tk >= 0) {
            const float* Mr = M + (size_t)tk * G3 + j0 + tx * 4;
#pragma unroll
            for (int g = 0; g < 3; g++) {
                float4 mf = *(const float4*)(Mr + g * En);
                m[g][0]=mf.x; m[g][1]=mf.y; m[g][2]=mf.z; m[g][3]=mf.w;
            }
        } else {
#pragma unroll
            for (int g = 0; g < 3; g++)
#pragma unroll
                for (int c = 0; c < 4; c++) m[g][c] = 0.f;
        }
        float acc[3][4];
#pragma unroll
        for (int g = 0; g < 3; g++) {
            unpack2(acc2[g][i][0], acc[g][0], acc[g][1]);
            unpack2(acc2[g][i][1], acc[g][2], acc[g][3]);
        }
        float4 hof = *(const float4*)(hin + (size_t)rr * En + j0 + tx * 4);
        float hold[4] = {hof.x, hof.y, hof.z, hof.w};
        float hnew[4];
#pragma unroll
        for (int c = 0; c < 4; c++) {
            float ir = m[0][c] + cv[0][c], hr = acc[0][c] + bh[0][c];
            float iz = m[1][c] + cv[1][c], hz = acc[1][c] + bh[1][c];
            float in_= m[2][c] + cv[2][c], hn = acc[2][c] + bh[2][c];
            float r = sigm(ir + hr);
            float z = sigm(iz + hz);
            float n = tanhf(in_ + r * hn);
            hnew[c] = (1.f - z) * n + z * hold[c];
        }
        *(float4*)(hout + (size_t)rr * En + j0 + tx * 4) = make_float4(hnew[0], hnew[1], hnew[2], hnew[3]);
    }
}

__global__ __launch_bounds__(256, 2) void k_logits(
    const float* __restrict__ hin, const float* __restrict__ We2d,
    const float* __restrict__ be2d, const float* __restrict__ unif,
    float* __restrict__ out, int t)
{
    __shared__ float As[2][16][68];
    __shared__ float Ws[2][16][132];
    __shared__ float sVal[64][17];
    __shared__ int   sIdx[64][17];
    const int tid = threadIdx.x;
    const int r0 = blockIdx.x * 64;
    const int ty = tid >> 4, tx = tid & 15;

    const int lr  = tid >> 2;
    const int lkq = (tid & 3) * 4;
    const float* Ag = hin + (size_t)(r0 + lr) * En + lkq;
    const int wn  = tid >> 1;
    const int wkq = (tid & 1) * 8;
    const float* Wg = We2d + (size_t)wn * En + wkq;

    float4 av = *(const float4*)Ag;
    float4 w0 = *(const float4*)Wg;
    float4 w1 = *(const float4*)(Wg + 4);

    ull acc2[4][4];
#pragma unroll
    for (int i = 0; i < 4; i++)
#pragma unroll
        for (int p = 0; p < 4; p++) acc2[i][p] = 0ull;

    As[0][lkq+0][lr] = av.x; As[0][lkq+1][lr] = av.y; As[0][lkq+2][lr] = av.z; As[0][lkq+3][lr] = av.w;
    Ws[0][wkq+0][wn] = w0.x; Ws[0][wkq+1][wn] = w0.y; Ws[0][wkq+2][wn] = w0.z; Ws[0][wkq+3][wn] = w0.w;
    Ws[0][wkq+4][wn] = w1.x; Ws[0][wkq+5][wn] = w1.y; Ws[0][wkq+6][wn] = w1.z; Ws[0][wkq+7][wn] = w1.w;
    __syncthreads();

    for (int kt = 0; kt < 16; kt++) {
        const int buf = kt & 1;
        if (kt < 15) {
            av = *(const float4*)(Ag + (kt + 1) * 16);
            w0 = *(const float4*)(Wg + (kt + 1) * 16);
            w1 = *(const float4*)(Wg + (kt + 1) * 16 + 4);
        }
#pragma unroll
        for (int k = 0; k < 16; k++) {
            float4 af = *(const float4*)&As[buf][k][ty * 4];
            ull ap[4];
            ap[0] = pack2(af.x, af.x); ap[1] = pack2(af.y, af.y);
            ap[2] = pack2(af.z, af.z); ap[3] = pack2(af.w, af.w);
            ull bp[4];
            bp[0] = *(const ull*)&Ws[buf][k][     tx * 4];
            bp[1] = *(const ull*)&Ws[buf][k][     tx * 4 + 2];
            bp[2] = *(const ull*)&Ws[buf][k][64 + tx * 4];
            bp[3] = *(const ull*)&Ws[buf][k][64 + tx * 4 + 2];
#pragma unroll
            for (int i = 0; i < 4; i++)
#pragma unroll
                for (int p = 0; p < 4; p++) fma2(acc2[i][p], ap[i], bp[p]);
        }
        if (kt < 15) {
            const int nb = buf ^ 1;
            As[nb][lkq+0][lr] = av.x; As[nb][lkq+1][lr] = av.y; As[nb][lkq+2][lr] = av.z; As[nb][lkq+3][lr] = av.w;
            Ws[nb][wkq+0][wn] = w0.x; Ws[nb][wkq+1][wn] = w0.y; Ws[nb][wkq+2][wn] = w0.z; Ws[nb][wkq+3][wn] = w0.w;
            Ws[nb][wkq+4][wn] = w1.x; Ws[nb][wkq+5][wn] = w1.y; Ws[nb][wkq+6][wn] = w1.z; Ws[nb][wkq+7][wn] = w1.w;
            __syncthreads();
        }
    }

    float be[8];
    {
        float4 b0 = *(const float4*)(be2d +      tx * 4);
        float4 b1 = *(const float4*)(be2d + 64 + tx * 4);
        be[0]=b0.x; be[1]=b0.y; be[2]=b0.z; be[3]=b0.w;
        be[4]=b1.x; be[5]=b1.y; be[6]=b1.z; be[7]=b1.w;
    }
#pragma unroll
    for (int i = 0; i < 4; i++) {
        const int rr = r0 + ty * 4 + i;
        const float* urow = unif + ((size_t)t * Bn + rr) * Vn;
        float acc[8];
        unpack2(acc2[i][0], acc[0], acc[1]);
        unpack2(acc2[i][1], acc[2], acc[3]);
        unpack2(acc2[i][2], acc[4], acc[5]);
        unpack2(acc2[i][3], acc[6], acc[7]);
        float best = -INFINITY; int bidx = Vn;
#pragma unroll
        for (int c = 0; c < 8; c++) {
            const int col = (c < 4) ? (tx * 4 + c) : (64 + tx * 4 + (c - 4));
            float u = urow[col];
            float g = -logf(-logf(u + 1e-10f) + 1e-10f);
            float v = acc[c] + be[c] + g;
            if (v > best || (v == best && col < bidx)) { best = v; bidx = col; }
        }
        sVal[ty * 4 + i][tx] = best;
        sIdx[ty * 4 + i][tx] = bidx;
    }
    __syncthreads();

    if (tid < 64) {
        const int b = r0 + tid;
        float best = sVal[tid][0]; int bidx = sIdx[tid][0];
#pragma unroll
        for (int j = 1; j < 16; j++) {
            float v = sVal[tid][j]; int ix = sIdx[tid][j];
            if (v > best || (v == best && ix < bidx)) { best = v; bidx = ix; }
        }
        bool ended = (bidx == 0);
        if (ended) g_N[b] = min(g_N[b], t);
        unsigned char an = (unsigned char)(g_alive[b] && !ended);
        g_alive[b] = an;
        int tk = an ? bidx : -1;
        g_tok[b] = tk;
        g_toks[t * Bn + b] = tk;
        if (an) out[(size_t)b * Tn * Vn + (size_t)t * Vn + bidx] = 1.0f;
    }
}

// ================= ENCODER: mma.sync bf16x3 gates + fused GRU =================
// CTA: 64 rows x 192-col permuted window. K=256 in 16 chunks of 16.
// smem per buffer: Ahi[64][24]h, Alo[64][24]h, Bhi[192][24]h, Blo[192][24]h = 24576B
// epilogue C_s: float[64][200] = 51200B (overlaps staging)
#define ST_AHI 0
#define ST_ALO 3072
#define ST_BHI 6144
#define ST_BLO 15360
#define EBUF   24576
#define EG_SMEM 51200

__global__ __launch_bounds__(256, 2) void k_egates(
    const float* __restrict__ hin, float* __restrict__ hout,
    const __nv_bfloat16* __restrict__ Bphi, const __nv_bfloat16* __restrict__ Bplo,
    const float* __restrict__ M, const float* __restrict__ cvec,
    const float* __restrict__ bhh, const int* __restrict__ tok)
{
    extern __shared__ char sm[];
    const int tid = threadIdx.x;
    const int wid = tid >> 5, lane = tid & 31;
    const int r0  = blockIdx.x * 64;
    const int win = blockIdx.y;

    const int m16 = (wid & 3) * 16;     // warp's row tile
    const int nh  = wid >> 2;           // warp's n-half (96 cols each)

    float acc[12][4];
#pragma unroll
    for (int j = 0; j < 12; j++)
#pragma unroll
        for (int p = 0; p < 4; p++) acc[j][p] = 0.f;

    // staging index math
    const int arow  = tid >> 2;          // 0..63
    const int koff4 = (tid & 3) * 4;     // 0,4,8,12
    const __nv_bfloat16* bsrc[2] = { Bphi + (size_t)win * 192 * En,
                                     Bplo + (size_t)win * 192 * En };

    float4 areg;
    uint4  breg[3];
    int    brow[3], bh8[3], bsp[3];
#pragma unroll
    for (int s = 0; s < 3; s++) {
        int idx = tid + s * 256;
        bsp[s]  = idx / 384;
        int rem = idx % 384;
        brow[s] = rem >> 1;
        bh8[s]  = rem & 1;
    }

    // prologue: load chunk 0
    areg = *(const float4*)(hin + (size_t)(r0 + arow) * En + koff4);
#pragma unroll
    for (int s = 0; s < 3; s++)
        breg[s] = *(const uint4*)(bsrc[bsp[s]] + (size_t)brow[s] * En + bh8[s] * 8);

    // store chunk 0 into buffer 0
    {
        char* base = sm;
        float hx = __bfloat162float(__float2bfloat16_rn(areg.x));
        float hy = __bfloat162float(__float2bfloat16_rn(areg.y));
        float hz = __bfloat162float(__float2bfloat16_rn(areg.z));
        float hw = __bfloat162float(__float2bfloat16_rn(areg.w));
        uint2 vhi = make_uint2(bfpack(areg.x, areg.y), bfpack(areg.z, areg.w));
        uint2 vlo = make_uint2(bfpack(areg.x - hx, areg.y - hy), bfpack(areg.z - hz, areg.w - hw));
        *(uint2*)(base + ST_AHI + arow * 48 + koff4 * 2) = vhi;
        *(uint2*)(base + ST_ALO + arow * 48 + koff4 * 2) = vlo;
#pragma unroll
        for (int s = 0; s < 3; s++) {
            int off = (bsp[s] ? ST_BLO : ST_BHI) + brow[s] * 48 + bh8[s] * 16;
            *(uint4*)(base + off) = breg[s];
        }
    }
    __syncthreads();

    const int fr  = lane >> 2;           // fragment row 0..7
    const int c2b = (lane & 3) * 4;      // fragment k byte offset

    for (int ch = 0; ch < 16; ch++) {
        const int cur = ch & 1;
        if (ch < 15) {
            const int k0 = (ch + 1) * 16;
            areg = *(const float4*)(hin + (size_t)(r0 + arow) * En + k0 + koff4);
#pragma unroll
            for (int s = 0; s < 3; s++)
                breg[s] = *(const uint4*)(bsrc[bsp[s]] + (size_t)brow[s] * En + k0 + bh8[s] * 8);
        }
        // compute on current buffer
        {
            const char* A_hi = sm + cur * EBUF + ST_AHI;
            const char* A_lo = sm + cur * EBUF + ST_ALO;
            const char* B_hi = sm + cur * EBUF + ST_BHI;
            const char* B_lo = sm + cur * EBUF + ST_BLO;
            const int abase = (m16 + fr) * 48 + c2b;
            uint32_t ah[4], al[4];
            ah[0] = *(const uint32_t*)(A_hi + abase);
            ah[1] = *(const uint32_t*)(A_hi + abase + 8 * 48);
            ah[2] = *(const uint32_t*)(A_hi + abase + 16);
            ah[3] = *(const uint32_t*)(A_hi + abase + 8 * 48 + 16);
            al[0] = *(const uint32_t*)(A_lo + abase);
            al[1] = *(const uint32_t*)(A_lo + abase + 8 * 48);
            al[2] = *(const uint32_t*)(A_lo + abase + 16);
            al[3] = *(const uint32_t*)(A_lo + abase + 8 * 48 + 16);
#pragma unroll
            for (int j = 0; j < 12; j++) {
                const int bbase = (nh * 96 + j * 8 + fr) * 48 + c2b;
                uint32_t bh0 = *(const uint32_t*)(B_hi + bbase);
                uint32_t bh1 = *(const uint32_t*)(B_hi + bbase + 16);
                uint32_t bl0 = *(const uint32_t*)(B_lo + bbase);
                uint32_t bl1 = *(const uint32_t*)(B_lo + bbase + 16);
                mma_bf16(acc[j], ah, bh0, bh1);
                mma_bf16(acc[j], ah, bl0, bl1);
                mma_bf16(acc[j], al, bh0, bh1);
            }
        }
        if (ch < 15) {
            char* base = sm + (cur ^ 1) * EBUF;
            float hx = __bfloat162float(__float2bfloat16_rn(areg.x));
            float hy = __bfloat162float(__float2bfloat16_rn(areg.y));
            float hz = __bfloat162float(__float2bfloat16_rn(areg.z));
            float hw = __bfloat162float(__float2bfloat16_rn(areg.w));
            uint2 vhi = make_uint2(bfpack(areg.x, areg.y), bfpack(areg.z, areg.w));
            uint2 vlo = make_uint2(bfpack(areg.x - hx, areg.y - hy), bfpack(areg.z - hz, areg.w - hw));
            *(uint2*)(base + ST_AHI + arow * 48 + koff4 * 2) = vhi;
            *(uint2*)(base + ST_ALO + arow * 48 + koff4 * 2) = vlo;
#pragma unroll
            for (int s = 0; s < 3; s++) {
                int off = (bsp[s] ? ST_BLO : ST_BHI) + brow[s] * 48 + bh8[s] * 16;
                *(uint4*)(base + off) = breg[s];
            }
            __syncthreads();
        }
    }

    // ---- epilogue: spill fragments to smem, then fused GRU ----
    __syncthreads();
    float* Cs = (float*)sm;
    {
        const int n2 = (lane & 3) * 2;
#pragma unroll
        for (int j = 0; j < 12; j++) {
            const int col = nh * 96 + j * 8 + n2;
            const int row = m16 + fr;
            *(float2*)&Cs[row * 200 + col]       = make_float2(acc[j][0], acc[j][1]);
            *(float2*)&Cs[(row + 8) * 200 + col] = make_float2(acc[j][2], acc[j][3]);
        }
    }
    __syncthreads();

    {
        const int row = tid & 63;
        const int cg  = tid >> 6;
        const int rr  = r0 + row;
        const int tk  = tok[rr];
        const float* Mr = M + (size_t)(tk >= 0 ? tk : 0) * G3;
#pragma unroll
        for (int cc = 0; cc < 16; cc++) {
            const int c = cg * 16 + cc;
            const int j = win * 64 + c;
            float rv = Cs[row * 200 + c];
            float zv = Cs[row * 200 + 64 + c];
            float nv = Cs[row * 200 + 128 + c];
            float mr = 0.f, mz = 0.f, mn = 0.f;
            if (tk >= 0) { mr = Mr[j]; mz = Mr[256 + j]; mn = Mr[512 + j]; }
            float ir = mr + cvec[j],       hr = rv + bhh[j];
            float iz = mz + cvec[256 + j], hz = zv + bhh[256 + j];
            float in_= mn + cvec[512 + j], hn = nv + bhh[512 + j];
            float r = sigm(ir + hr);
            float z = sigm(iz + hz);
            float n = tanhf(in_ + r * hn);
            float hold = hin[(size_t)rr * En + j];
            hout[(size_t)rr * En + j] = (1.f - z) * n + z * hold;
        }
    }
}

// ---------------- final ----------------
__global__ void k_final(float* __restrict__ out) {
    int i = blockIdx.x * blockDim.x + threadIdx.x;
    if (i < Bn * En) out[OUT_ROFF + i] = g_he[0][i];
    if (i < Bn)      out[OUT_NOFF + i] = (float)g_N[i];
}

// ---------------- host ----------------
extern "C" void kernel_launch(void* const* d_in, const int* in_sizes, int n_in,
                              void* d_out, int out_size) {
    const float* x        = (const float*)d_in[0];
    const float* unif     = (const float*)d_in[2];
    const float* dec_Wd2e = (const float*)d_in[3];
    const float* dec_bd2e = (const float*)d_in[4];
    const float* dec_Wih  = (const float*)d_in[5];
    const float* dec_Whh  = (const float*)d_in[6];
    const float* dec_bih  = (const float*)d_in[7];
    const float* dec_bhh  = (const float*)d_in[8];
    const float* dec_We2d = (const float*)d_in[9];
    const float* dec_be2d = (const float*)d_in[10];
    const float* enc_Wd2e = (const float*)d_in[11];
    const float* enc_bd2e = (const float*)d_in[12];
    const float* enc_Wih  = (const float*)d_in[13];
    const float* enc_Whh  = (const float*)d_in[14];
    const float* enc_bih  = (const float*)d_in[15];
    const float* enc_bhh  = (const float*)d_in[16];
    float* out = (float*)d_out;

    void *p_h, *p_he, *p_Mdec, *p_cdec, *p_Menc, *p_cenc, *p_tok, *p_toks, *p_bhi, *p_blo;
    cudaGetSymbolAddress(&p_h,    g_h);
    cudaGetSymbolAddress(&p_he,   g_he);
    cudaGetSymbolAddress(&p_Mdec, g_Mdec);
    cudaGetSymbolAddress(&p_cdec, g_cdec);
    cudaGetSymbolAddress(&p_Menc, g_Menc);
    cudaGetSymbolAddress(&p_cenc, g_cenc);
    cudaGetSymbolAddress(&p_tok,  g_tok);
    cudaGetSymbolAddress(&p_toks, g_toks);
    cudaGetSymbolAddress(&p_bhi,  g_eBhi);
    cudaGetSymbolAddress(&p_blo,  g_eBlo);
    float* hb[2]  = { (float*)p_h,  (float*)p_h  + (size_t)Bn * En };
    float* heb[2] = { (float*)p_he, (float*)p_he + (size_t)Bn * En };
    float* Mdec = (float*)p_Mdec; float* cdec = (float*)p_cdec;
    float* Menc = (float*)p_Menc; float* cenc = (float*)p_cenc;
    __nv_bfloat16* eBhi = (__nv_bfloat16*)p_bhi;
    __nv_bfloat16* eBlo = (__nv_bfloat16*)p_blo;
    int* tok = (int*)p_tok; int* toks = (int*)p_toks;

    static int smem_set = 0;
    if (!smem_set) {
        cudaFuncSetAttribute(k_egates, cudaFuncAttributeMaxDynamicSharedMemorySize, EG_SMEM);
        smem_set = 1;
    }

    const int NT = 256;
    const int gBE = (Bn * En + NT - 1) / NT;
    int gz = (int)((OUT_UTT / 4 + NT - 1) / NT);

    k_zero_out<<<gz, NT>>>(out);
    k_init<<<gBE, NT>>>(x);
    k_prep<<<dim3(Vn, G3 / 64), NT>>>(dec_Wih, dec_Wd2e, dec_bd2e, dec_bih, Mdec, cdec);
    k_prep<<<dim3(Vn, G3 / 64), NT>>>(enc_Wih, enc_Wd2e, enc_bd2e, enc_bih, Menc, cenc);
    k_prepB<<<(4 * 192 * En + NT - 1) / NT, NT>>>(enc_Whh, eBhi, eBlo);

    dim3 gGates(Bn / 64, 4);
    dim3 gLog(Bn / 64);

    for (int t = 0; t < Tn; t++) {
        k_gates<<<gGates, NT>>>(hb[t & 1], hb[(t + 1) & 1], dec_Whh, dec_bhh, Mdec, cdec, tok);
        k_logits<<<gLog, NT>>>(hb[(t + 1) & 1], dec_We2d, dec_be2d, unif, out, t);
    }
    for (int t = 0; t < Tn; t++) {
        k_egates<<<dim3(Bn / 64, 4), NT, EG_SMEM>>>(heb[t & 1], heb[(t + 1) & 1],
                                                    eBhi, eBlo, Menc, cenc, enc_bhh,
                                                    toks + t * Bn);
    }
    k_final<<<gBE, NT>>>(out);
}